// round 2
// baseline (speedup 1.0000x reference)
#include <cuda_runtime.h>

// Cost volume: out[b,k,h,w] = (1/81) * sum_c x1[b,c,h,w] * x2[b,c,h-i,w-j]
//   i,j in [-4,4], k = (9i+j) mod 81. Zero padding outside image bounds.
// Shapes: B=4, C=128, H=128, W=256, D=81. fp32.
//
// R1 design: 3-way i-split across CTAs (108 accs), 4 px/thread, LDS.128
// window loads, 10-row x2 halo, launch_bounds(128,3) for 3 CTAs/SM.

#define Bn 4
#define Cn 128
#define Hn 128
#define Wn 256
#define Dn 81
#define TH 8
#define TW 64          // tile width (4 px per thread * 16 threads)
#define CC 8           // channels per smem chunk
#define NTHR 128
#define S2W 72         // TW + 8 halo
#define S2H 10         // TH + 2 (contiguous 3-i group)

__global__ __launch_bounds__(NTHR, 3)
void costvol_kernel(const float* __restrict__ x1,
                    const float* __restrict__ x2,
                    float* __restrict__ out) {
    __shared__ __align__(16) float s1[CC][TH][TW];     // 16 KB
    __shared__ __align__(16) float s2[CC][S2H][S2W];   // 23.0 KB

    const int wt = blockIdx.x / 3;          // 4 w-tiles
    const int g  = blockIdx.x - wt * 3;     // i-group 0..2 (adjacent -> L2 reuse)
    const int w0 = wt * TW;
    const int h0 = blockIdx.y * TH;         // 16 h-tiles
    const int b  = blockIdx.z;              // 4 batches

    const int tid = threadIdx.x;
    const int tx  = tid & 15;               // 16 groups of 4 pixels
    const int ty  = tid >> 4;               // 8 rows

    // x2 rows needed for this group: base2 + 0..9
    const int base2 = h0 + 2 - 3 * g;

    float acc[3][9][4];
#pragma unroll
    for (int u = 0; u < 3; u++)
#pragma unroll
        for (int jj = 0; jj < 9; jj++)
#pragma unroll
            for (int p = 0; p < 4; p++) acc[u][jj][p] = 0.f;

    for (int c0 = 0; c0 < Cn; c0 += CC) {
        // ---- s1: CC*TH*TW/4 = 1024 float4, 8 per thread ----
#pragma unroll
        for (int q = 0; q < 8; q++) {
            int f   = tid + q * NTHR;       // 0..1023
            int cc  = f >> 7;               // 128 float4 per channel
            int rem = f & 127;
            int hh  = rem >> 4;             // 16 float4 per row
            int k4  = rem & 15;
            const float4 v = *(const float4*)(x1 +
                (((size_t)((b * Cn + c0 + cc) * Hn + h0 + hh)) * Wn + w0 + 4 * k4));
            *(float4*)&s1[cc][hh][4 * k4] = v;
        }
        // ---- s2: CC*S2H*S2W/4 = 1440 float4 ----
#pragma unroll
        for (int q = 0; q < 12; q++) {
            int f = tid + q * NTHR;
            if (f < CC * S2H * (S2W / 4)) {
                int cc  = f / (S2H * (S2W / 4));
                int rem = f - cc * (S2H * (S2W / 4));
                int r   = rem / (S2W / 4);
                int k4  = rem - r * (S2W / 4);
                int hg  = base2 + r;
                int wg  = w0 - 4 + 4 * k4;  // float4-aligned
                float4 v = make_float4(0.f, 0.f, 0.f, 0.f);
                if ((unsigned)hg < (unsigned)Hn && (unsigned)wg < (unsigned)Wn)
                    v = *(const float4*)(x2 +
                        (((size_t)((b * Cn + c0 + cc) * Hn + hg)) * Wn + wg));
                *(float4*)&s2[cc][r][4 * k4] = v;
            }
        }
        __syncthreads();

        // ---- compute ----
#pragma unroll 2
        for (int cc = 0; cc < CC; cc++) {
            const float4 av = *(const float4*)&s1[cc][ty][4 * tx];
            const float a[4] = {av.x, av.y, av.z, av.w};
#pragma unroll
            for (int u = 0; u < 3; u++) {
                // local x2 row for ii = 3g+u: r = ty + 2 - u
                const float* rp = &s2[cc][ty + 2 - u][4 * tx];
                float wnd[12];
#pragma unroll
                for (int m = 0; m < 12; m += 4) {
                    float4 t = *(const float4*)(rp + m);   // aligned LDS.128
                    wnd[m] = t.x; wnd[m + 1] = t.y; wnd[m + 2] = t.z; wnd[m + 3] = t.w;
                }
#pragma unroll
                for (int jj = 0; jj < 9; jj++) {
#pragma unroll
                    for (int p = 0; p < 4; p++)
                        acc[u][jj][p] += a[p] * wnd[p + 8 - jj];
                }
            }
        }
        __syncthreads();
    }

    // ---- epilogue: k = (9*ii + jj + 41) % 81, ii = 3g+u ----
    const float inv = 1.0f / 81.0f;
    const int hg = h0 + ty;
    const int wg = w0 + 4 * tx;
#pragma unroll
    for (int u = 0; u < 3; u++) {
        const int ii = 3 * g + u;
#pragma unroll
        for (int jj = 0; jj < 9; jj++) {
            const int k = (9 * ii + jj + 41) % 81;
            float4 v = make_float4(acc[u][jj][0] * inv, acc[u][jj][1] * inv,
                                   acc[u][jj][2] * inv, acc[u][jj][3] * inv);
            *(float4*)(out + (((size_t)((b * Dn + k) * Hn + hg)) * Wn + wg)) = v;
        }
    }
}

extern "C" void kernel_launch(void* const* d_in, const int* in_sizes, int n_in,
                              void* d_out, int out_size) {
    (void)in_sizes; (void)n_in; (void)out_size;
    const float* x1 = (const float*)d_in[0];
    const float* x2 = (const float*)d_in[1];
    float* out = (float*)d_out;
    dim3 grid((Wn / TW) * 3, Hn / TH, Bn);   // (12, 16, 4) = 768 blocks
    costvol_kernel<<<grid, NTHR>>>(x1, x2, out);
}

// round 3
// speedup vs baseline: 3.9076x; 3.9076x over previous
#include <cuda_runtime.h>
#include <cstdint>

// Cost volume: out[b,k,h,w] = (1/81) * sum_c x1[b,c,h,w] * x2[b,c,h-i,w-j]
//   i,j in [-4,4], k = (9i+j) mod 81. Zero padding. B=4,C=128,H=128,W=256,D=81.
//
// R2: one CTA = 8h?no: 4h x 64w tile, 192 threads = 3 warp-groups of 64.
// Group g handles i in {3g, 3g+1, 3g+2}; all groups share smem tiles (no
// global redundancy). P=4 px/thread, 108 reg accumulators, cp.async
// double-buffered channel chunks of 4.

#define Bn 4
#define Cn 128
#define Hn 128
#define Wn 256
#define Dn 81
#define TH 4
#define TW 64
#define CC 4
#define NCH (Cn / CC)       // 32 chunks
#define S2H (TH + 8)        // 12
#define S2W (TW + 8)        // 72
#define NTHR 192

#define S1_F4 (CC * TH * TW / 4)    // 256
#define S2_F4 (CC * S2H * S2W / 4)  // 864

__device__ __forceinline__ void cp16(uint32_t saddr, const float* gptr, bool ok) {
    int sz = ok ? 16 : 0;
    asm volatile("cp.async.cg.shared.global [%0], [%1], 16, %2;\n"
                 :: "r"(saddr), "l"(gptr), "r"(sz));
}
__device__ __forceinline__ void cp_commit() {
    asm volatile("cp.async.commit_group;\n" ::: "memory");
}
template <int N>
__device__ __forceinline__ void cp_wait() {
    asm volatile("cp.async.wait_group %0;\n" :: "n"(N) : "memory");
}

__global__ __launch_bounds__(NTHR, 2)
void costvol_kernel(const float* __restrict__ x1,
                    const float* __restrict__ x2,
                    float* __restrict__ out) {
    __shared__ __align__(16) float s1[2][CC][TH][TW];   // 2*4KB
    __shared__ __align__(16) float s2[2][CC][S2H][S2W]; // 2*13.5KB

    const int w0 = blockIdx.x * TW;
    const int h0 = blockIdx.y * TH;
    const int b  = blockIdx.z;

    const int tid = threadIdx.x;
    const int g   = tid / 64;        // i-group 0..2
    const int r   = tid - g * 64;
    const int tx  = r & 15;          // 16 pixel-quads across w
    const int ty  = r >> 4;          // 4 rows

    const float* x1b = x1 + (size_t)(b * Cn) * Hn * Wn;
    const float* x2b = x2 + (size_t)(b * Cn) * Hn * Wn;

    // ---- prefetch helper (inlined twice via lambda) ----
    auto prefetch = [&](int c0, int st) {
        // s1: 256 float4
#pragma unroll
        for (int q = 0; q < 2; q++) {
            int f = tid + q * NTHR;
            if (f < S1_F4) {
                int cc  = f >> 6;
                int rem = f & 63;
                int hh  = rem >> 4;
                int k4  = rem & 15;
                uint32_t sa = (uint32_t)__cvta_generic_to_shared(&s1[st][cc][hh][4 * k4]);
                cp16(sa, x1b + (((size_t)(c0 + cc) * Hn + h0 + hh) * Wn + w0 + 4 * k4), true);
            }
        }
        // s2: 864 float4 (12 rows with +-4 h halo, 72-wide with +-4 w halo)
#pragma unroll
        for (int q = 0; q < 5; q++) {
            int f = tid + q * NTHR;
            if (f < S2_F4) {
                int cc  = f / (S2H * (S2W / 4));
                int rem = f - cc * (S2H * (S2W / 4));
                int row = rem / (S2W / 4);
                int k4  = rem - row * (S2W / 4);
                int hg  = h0 - 4 + row;
                int wg  = w0 - 4 + 4 * k4;
                bool ok = ((unsigned)hg < (unsigned)Hn) && ((unsigned)wg < (unsigned)Wn);
                const float* gp = ok ? (x2b + (((size_t)cc + c0) * Hn + hg) * (size_t)Wn + wg)
                                     : x2b;
                uint32_t sa = (uint32_t)__cvta_generic_to_shared(&s2[st][cc][row][4 * k4]);
                cp16(sa, gp, ok);
            }
        }
        cp_commit();
    };

    float acc[3][9][4];
#pragma unroll
    for (int u = 0; u < 3; u++)
#pragma unroll
        for (int jj = 0; jj < 9; jj++)
#pragma unroll
            for (int p = 0; p < 4; p++) acc[u][jj][p] = 0.f;

    prefetch(0, 0);

    for (int it = 0; it < NCH; it++) {
        const int st = it & 1;
        if (it + 1 < NCH) {
            prefetch((it + 1) * CC, st ^ 1);
            cp_wait<1>();
        } else {
            cp_wait<0>();
        }
        __syncthreads();   // chunk `it` visible to all

#pragma unroll
        for (int cc = 0; cc < CC; cc++) {
            const float4 av = *(const float4*)&s1[st][cc][ty][4 * tx];
            const float a[4] = {av.x, av.y, av.z, av.w};
#pragma unroll
            for (int u = 0; u < 3; u++) {
                // local x2 row for ii = 3g+u:  ty + 8 - ii
                const float* rp = &s2[st][cc][ty + 8 - 3 * g - u][4 * tx];
                float wnd[12];
#pragma unroll
                for (int m = 0; m < 12; m += 4) {
                    float4 t = *(const float4*)(rp + m);   // aligned LDS.128
                    wnd[m] = t.x; wnd[m + 1] = t.y; wnd[m + 2] = t.z; wnd[m + 3] = t.w;
                }
#pragma unroll
                for (int jj = 0; jj < 9; jj++) {
#pragma unroll
                    for (int p = 0; p < 4; p++)
                        acc[u][jj][p] += a[p] * wnd[p + 8 - jj];
                }
            }
        }
        __syncthreads();   // all readers done before stage st is refilled
    }

    // ---- epilogue: k = (9*ii + jj + 41) mod 81, ii = 3g+u ----
    const float inv = 1.0f / 81.0f;
    const int hg = h0 + ty;
    const int wg = w0 + 4 * tx;
#pragma unroll
    for (int u = 0; u < 3; u++) {
        const int ii = 3 * g + u;
#pragma unroll
        for (int jj = 0; jj < 9; jj++) {
            int k = 9 * ii + jj + 41;
            if (k >= 81) k -= 81;
            float4 v = make_float4(acc[u][jj][0] * inv, acc[u][jj][1] * inv,
                                   acc[u][jj][2] * inv, acc[u][jj][3] * inv);
            *(float4*)(out + (((size_t)((b * Dn + k) * Hn + hg)) * Wn + wg)) = v;
        }
    }
}

extern "C" void kernel_launch(void* const* d_in, const int* in_sizes, int n_in,
                              void* d_out, int out_size) {
    (void)in_sizes; (void)n_in; (void)out_size;
    const float* x1 = (const float*)d_in[0];
    const float* x2 = (const float*)d_in[1];
    float* out = (float*)d_out;
    dim3 grid(Wn / TW, Hn / TH, Bn);   // (4, 32, 4) = 512 blocks
    costvol_kernel<<<grid, NTHR>>>(x1, x2, out);
}